// round 1
// baseline (speedup 1.0000x reference)
#include <cuda_runtime.h>
#include <cuda_bf16.h>
#include <cstdint>

// Problem constants
#define B_SZ   1024
#define T_SZ   4
#define D_IN   768
#define D_SAE  16384
#define K_TOP  64
#define K_DIM  (T_SZ * D_IN)        // 3072  (GEMM K)
#define TD     (T_SZ * D_IN)        // 3072  (decode output per row)

// Scratch for compacted top-k lists (device globals: no allocation allowed)
__device__ int   g_idx[B_SZ * K_TOP];
__device__ float g_val[B_SZ * K_TOP];

// ---------------------------------------------------------------------------
// Kernel 1: encode GEMM  pre = relu(X(1024x3072) @ W(3072x16384) + b_enc)
// Classic 128x128x8 register-blocked SGEMM, writes relu'd result into z.
// ---------------------------------------------------------------------------
#define BM 128
#define BN 128
#define BK 8
#define TM 8
#define TN 8

__global__ __launch_bounds__(256) void encode_gemm_kernel(
    const float* __restrict__ A,     // (1024, 3072)
    const float* __restrict__ Bm,    // (3072, 16384)  == W_enc flattened
    const float* __restrict__ bias,  // (16384)
    float* __restrict__ C)           // (1024, 16384)  -> z region
{
    const int M = B_SZ, N = D_SAE, K = K_DIM;

    __shared__ float As[BK][BM];
    __shared__ float Bs[BK][BN];

    const int tid  = threadIdx.x;
    const int cRow = blockIdx.y;   // 0..7
    const int cCol = blockIdx.x;   // 0..127

    const float* Ab = A  + (size_t)cRow * BM * K;
    const float* Bb = Bm + (size_t)cCol * BN;

    // Global->shared load mapping (one float4 per thread per tile)
    const int aRow = tid >> 1;          // 0..127
    const int aCol = (tid & 1) * 4;     // 0 or 4
    const int bRow = tid >> 5;          // 0..7
    const int bCol = (tid & 31) * 4;    // 0..124

    const int tRow = (tid >> 4) * TM;   // 0..120
    const int tCol = (tid & 15) * TN;   // 0..120

    float acc[TM][TN] = {};

    for (int k0 = 0; k0 < K; k0 += BK) {
        float4 a = *reinterpret_cast<const float4*>(Ab + (size_t)aRow * K + k0 + aCol);
        As[aCol + 0][aRow] = a.x;
        As[aCol + 1][aRow] = a.y;
        As[aCol + 2][aRow] = a.z;
        As[aCol + 3][aRow] = a.w;
        float4 bv = *reinterpret_cast<const float4*>(Bb + (size_t)(k0 + bRow) * N + bCol);
        *reinterpret_cast<float4*>(&Bs[bRow][bCol]) = bv;
        __syncthreads();

        #pragma unroll
        for (int k = 0; k < BK; k++) {
            float rm[TM], rn[TN];
            #pragma unroll
            for (int i = 0; i < TM; i++) rm[i] = As[k][tRow + i];
            #pragma unroll
            for (int j = 0; j < TN; j++) rn[j] = Bs[k][tCol + j];
            #pragma unroll
            for (int i = 0; i < TM; i++)
                #pragma unroll
                for (int j = 0; j < TN; j++)
                    acc[i][j] = fmaf(rm[i], rn[j], acc[i][j]);
        }
        __syncthreads();
    }

    // Epilogue: + bias, relu, vectorized store
    const int colBase = cCol * BN + tCol;
    float bl[TN];
    #pragma unroll
    for (int j = 0; j < TN; j++) bl[j] = bias[colBase + j];

    #pragma unroll
    for (int i = 0; i < TM; i++) {
        float* cp = C + (size_t)(cRow * BM + tRow + i) * N + colBase;
        #pragma unroll
        for (int j4 = 0; j4 < TN; j4 += 4) {
            float4 v;
            v.x = fmaxf(acc[i][j4 + 0] + bl[j4 + 0], 0.0f);
            v.y = fmaxf(acc[i][j4 + 1] + bl[j4 + 1], 0.0f);
            v.z = fmaxf(acc[i][j4 + 2] + bl[j4 + 2], 0.0f);
            v.w = fmaxf(acc[i][j4 + 3] + bl[j4 + 3], 0.0f);
            *reinterpret_cast<float4*>(cp + j4) = v;
        }
    }
}

// ---------------------------------------------------------------------------
// Kernel 2: per-row exact top-64 via 4-pass radix select on float bits.
// All values are >= 0 (post-relu), so uint bit order == float order.
// Zeroes non-selected entries of z in place; emits compact (idx,val) lists.
// ---------------------------------------------------------------------------
__global__ __launch_bounds__(256) void topk_kernel(float* __restrict__ z)
{
    const int D = D_SAE;
    const int b = blockIdx.x;
    float* row = z + (size_t)b * D;
    const int tid = threadIdx.x;

    __shared__ unsigned int hist[256];
    __shared__ unsigned int sh_prefix;
    __shared__ int sh_kRemain;
    __shared__ int sh_cnt_eq;
    __shared__ int sh_slot;

    if (tid == 0) { sh_prefix = 0u; sh_kRemain = K_TOP; }
    __syncthreads();

    for (int shift = 24; shift >= 0; shift -= 8) {
        hist[tid] = 0u;
        __syncthreads();
        const unsigned int prefix = sh_prefix;
        const unsigned int hmask  = (shift == 24) ? 0u : (0xFFFFFFFFu << (shift + 8));
        for (int i = tid; i < D; i += 256) {
            unsigned int bits = __float_as_uint(row[i]);
            if ((bits & hmask) == prefix)
                atomicAdd(&hist[(bits >> shift) & 0xFF], 1u);
        }
        __syncthreads();
        if (tid == 0) {
            int cum = 0;
            const int kr = sh_kRemain;
            for (int bin = 255; bin >= 0; bin--) {
                cum += (int)hist[bin];
                if (cum >= kr) {
                    sh_kRemain = kr - (cum - (int)hist[bin]); // still needed from this bin
                    sh_prefix  = prefix | ((unsigned int)bin << shift);
                    break;
                }
            }
        }
        __syncthreads();
    }

    const unsigned int thresh = sh_prefix;
    const int need_eq = sh_kRemain;
    if (tid == 0) { sh_cnt_eq = 0; sh_slot = 0; }
    __syncthreads();

    for (int i = tid; i < D; i += 256) {
        const float v = row[i];
        const unsigned int bits = __float_as_uint(v);
        bool keep = false;
        if (bits > thresh) {
            keep = true;
        } else if (bits == thresh) {
            int p = atomicAdd(&sh_cnt_eq, 1);
            keep = (p < need_eq);
        }
        if (keep) {
            int s = atomicAdd(&sh_slot, 1);
            if (s < K_TOP) {
                g_idx[b * K_TOP + s] = i;
                g_val[b * K_TOP + s] = v;
            }
        } else {
            row[i] = 0.0f;
        }
    }
}

// ---------------------------------------------------------------------------
// Kernel 3: sparse decode.  x_hat[b, t, d] = b_dec[t,d] + sum_s val*W_dec[t,m,d]
// One block per batch row; 256 threads, 12 outputs per thread (3072 total).
// ---------------------------------------------------------------------------
__global__ __launch_bounds__(256) void decode_kernel(
    const float* __restrict__ W_dec,  // (T, D_SAE, D_IN)
    const float* __restrict__ b_dec,  // (T, D_IN)
    float* __restrict__ xhat)         // (B, T, D_IN)
{
    const int b = blockIdx.x;
    const int tid = threadIdx.x;

    __shared__ float sv[K_TOP];
    __shared__ int   si[K_TOP];
    if (tid < K_TOP) {
        sv[tid] = g_val[b * K_TOP + tid];
        si[tid] = g_idx[b * K_TOP + tid];
    }

    float  acc[12];
    size_t off[12];
    #pragma unroll
    for (int s = 0; s < 12; s++) {
        const int o = tid + s * 256;      // 0..3071
        const int t = o / D_IN;
        const int d = o - t * D_IN;
        off[s] = (size_t)t * D_SAE * D_IN + d;
        acc[s] = b_dec[o];
    }
    __syncthreads();

    for (int i = 0; i < K_TOP; i++) {
        const float v = sv[i];
        const size_t mo = (size_t)si[i] * D_IN;
        #pragma unroll
        for (int s = 0; s < 12; s++)
            acc[s] = fmaf(v, __ldg(W_dec + off[s] + mo), acc[s]);
    }

    float* out = xhat + (size_t)b * TD;
    #pragma unroll
    for (int s = 0; s < 12; s++)
        out[tid + s * 256] = acc[s];
}

// ---------------------------------------------------------------------------
// Launch
// ---------------------------------------------------------------------------
extern "C" void kernel_launch(void* const* d_in, const int* in_sizes, int n_in,
                              void* d_out, int out_size)
{
    const float* x     = (const float*)d_in[0];  // (B, T, D_IN)
    const float* W_enc = (const float*)d_in[1];  // (T, D_IN, D_SAE) == (3072, 16384)
    const float* b_enc = (const float*)d_in[2];  // (D_SAE)
    const float* W_dec = (const float*)d_in[3];  // (T, D_SAE, D_IN)
    const float* b_dec = (const float*)d_in[4];  // (T, D_IN)

    float* xhat = (float*)d_out;                       // first output: (B, T, D_IN)
    float* z    = xhat + (size_t)B_SZ * TD;            // second output: (B, D_SAE)

    dim3 gemmGrid(D_SAE / BN, B_SZ / BM);  // (128, 8)
    encode_gemm_kernel<<<gemmGrid, 256>>>(x, W_enc, b_enc, z);
    topk_kernel<<<B_SZ, 256>>>(z);
    decode_kernel<<<B_SZ, 256>>>(W_dec, b_dec, xhat);
}

// round 3
// speedup vs baseline: 2.3328x; 2.3328x over previous
#include <cuda_runtime.h>
#include <cuda_bf16.h>
#include <cstdint>

// Problem constants
#define B_SZ   1024
#define T_SZ   4
#define D_IN   768
#define D_SAE  16384
#define K_TOP  64
#define K_DIM  3072
#define TD     3072

// ---------------------------------------------------------------------------
// Device scratch (no allocation allowed)
// ---------------------------------------------------------------------------
__device__ __nv_bfloat16 g_xhi[B_SZ * K_DIM];
__device__ __nv_bfloat16 g_xlo[B_SZ * K_DIM];
__device__ __nv_bfloat16 g_whi[(size_t)D_SAE * K_DIM];   // W^T hi, (N, K) row-major
__device__ __nv_bfloat16 g_wlo[(size_t)D_SAE * K_DIM];   // W^T lo
__device__ int   g_idx[B_SZ * K_TOP];
__device__ float g_val[B_SZ * K_TOP];

// ---------------------------------------------------------------------------
// PTX helpers (base sm_80+ features only: cp.async, ldmatrix, mma.sync)
// ---------------------------------------------------------------------------
static __device__ __forceinline__ uint32_t smem_u32(const void* p) {
    uint32_t a;
    asm("{ .reg .u64 t; cvta.to.shared.u64 t, %1; cvt.u32.u64 %0, t; }" : "=r"(a) : "l"(p));
    return a;
}
static __device__ __forceinline__ void cp16(uint32_t dst, const void* src) {
    asm volatile("cp.async.cg.shared.global [%0], [%1], 16;" :: "r"(dst), "l"(src));
}
#define CP_COMMIT() asm volatile("cp.async.commit_group;" ::: "memory")
#define CP_WAIT2()  asm volatile("cp.async.wait_group 2;" ::: "memory")

static __device__ __forceinline__ void ldm4(uint32_t* r, uint32_t addr) {
    asm volatile("ldmatrix.sync.aligned.m8n8.x4.shared.b16 {%0,%1,%2,%3}, [%4];"
                 : "=r"(r[0]), "=r"(r[1]), "=r"(r[2]), "=r"(r[3]) : "r"(addr));
}
static __device__ __forceinline__ void mma16816(float* c, const uint32_t* a, const uint32_t* b) {
    asm volatile(
        "mma.sync.aligned.m16n8k16.row.col.f32.bf16.bf16.f32 "
        "{%0,%1,%2,%3}, {%4,%5,%6,%7}, {%8,%9}, {%0,%1,%2,%3};"
        : "+f"(c[0]), "+f"(c[1]), "+f"(c[2]), "+f"(c[3])
        : "r"(a[0]), "r"(a[1]), "r"(a[2]), "r"(a[3]), "r"(b[0]), "r"(b[1]));
}

// ---------------------------------------------------------------------------
// Split kernels (fp32 -> bf16 hi/lo); W also transposed to (N, K) K-major
// ---------------------------------------------------------------------------
__global__ __launch_bounds__(256) void split_x_kernel(const float* __restrict__ x) {
    int i = blockIdx.x * 256 + threadIdx.x;
    float v = x[i];
    __nv_bfloat16 h = __float2bfloat16(v);
    g_xhi[i] = h;
    g_xlo[i] = __float2bfloat16(v - __bfloat162float(h));
}

__global__ __launch_bounds__(256) void split_w_kernel(const float* __restrict__ W) {
    __shared__ float t[32][33];
    const int n0 = blockIdx.x * 32, k0 = blockIdx.y * 32;
    const int tx = threadIdx.x & 31, ty = threadIdx.x >> 5;
    #pragma unroll
    for (int j = 0; j < 4; j++)
        t[ty + j * 8][tx] = W[(size_t)(k0 + ty + j * 8) * D_SAE + n0 + tx];
    __syncthreads();
    #pragma unroll
    for (int j = 0; j < 4; j++) {
        const int nl = ty + j * 8;
        float v = t[tx][nl];
        __nv_bfloat16 h = __float2bfloat16(v);
        size_t o = (size_t)(n0 + nl) * K_DIM + k0 + tx;
        g_whi[o] = h;
        g_wlo[o] = __float2bfloat16(v - __bfloat162float(h));
    }
}

// ---------------------------------------------------------------------------
// Encode GEMM via mma.sync (HMMA): C = relu(X @ W + b), 3-product bf16 split.
// 128x128 CTA tile, BK=32, 3-stage cp.async pipeline.
// Smem rows padded to 80B so all ldmatrix 8-row groups are conflict-free.
// ---------------------------------------------------------------------------
#define LDB     80                       // bytes per 32-element bf16 row (64 + 16 pad)
#define MAT_B   (128 * LDB)              // 10240 bytes per matrix tile
#define A_HI    0
#define A_LO    (MAT_B)
#define B_HI    (2 * MAT_B)
#define B_LO    (3 * MAT_B)
#define STAGE_B (4 * MAT_B)              // 40960
#define STAGES  3
#define NITER   (K_DIM / 32)             // 96
#define SMEM_DYN (STAGES * STAGE_B)      // 122880

static __device__ __forceinline__ void load_stage(
    uint32_t st, const __nv_bfloat16* Ah, const __nv_bfloat16* Al,
    const __nv_bfloat16* Bh, const __nv_bfloat16* Bl, int tid, int k0)
{
    #pragma unroll
    for (int i = 0; i < 2; i++) {
        const int j   = tid + i * 256;       // 0..511
        const int row = j >> 2, seg = j & 3;
        const uint32_t so = row * LDB + seg * 16;
        const size_t   go = (size_t)row * K_DIM + k0 + seg * 8;
        cp16(st + A_HI + so, Ah + go);
        cp16(st + A_LO + so, Al + go);
        cp16(st + B_HI + so, Bh + go);
        cp16(st + B_LO + so, Bl + go);
    }
    CP_COMMIT();
}

__global__ __launch_bounds__(256) void encode_mma_kernel(
    const float* __restrict__ bias, float* __restrict__ C)
{
    extern __shared__ __align__(128) char smem[];
    const uint32_t sb = smem_u32(smem);
    const int tid = threadIdx.x, wid = tid >> 5, lane = tid & 31;
    const int wm = wid >> 2, wn = wid & 3;         // warp grid 2(M) x 4(N)
    const int bn = blockIdx.x, bm = blockIdx.y;

    const __nv_bfloat16* Ah = g_xhi + (size_t)bm * 128 * K_DIM;
    const __nv_bfloat16* Al = g_xlo + (size_t)bm * 128 * K_DIM;
    const __nv_bfloat16* Bh = g_whi + (size_t)bn * 128 * K_DIM;
    const __nv_bfloat16* Bl = g_wlo + (size_t)bn * 128 * K_DIM;

    // ldmatrix lane address components
    const uint32_t a_off = (uint32_t)((lane & 15) * LDB + (lane >> 4) * 16);
    const uint32_t b_row = (uint32_t)((lane & 7) + (lane >> 4) * 8);
    const uint32_t b_kh  = (uint32_t)(((lane >> 3) & 1) * 16);

    float acc[4][4][4] = {};

    // Prologue: fill 3 stages
    for (int s = 0; s < STAGES; s++)
        load_stage(sb + s * STAGE_B, Ah, Al, Bh, Bl, tid, s * 32);

    for (int it = 0; it < NITER; ++it) {
        CP_WAIT2();
        __syncthreads();
        const uint32_t st = sb + (it % 3) * STAGE_B;

        #pragma unroll
        for (int ks = 0; ks < 2; ks++) {
            const uint32_t kb = ks * 32;
            uint32_t ah[4][4], al[4][4], bh[4][2], bl[4][2];
            #pragma unroll
            for (int mt = 0; mt < 4; mt++) {
                const uint32_t r = (wm * 64 + mt * 16) * LDB + a_off + kb;
                ldm4(ah[mt], st + A_HI + r);
                ldm4(al[mt], st + A_LO + r);
            }
            #pragma unroll
            for (int p = 0; p < 2; p++) {
                const uint32_t r = (wn * 32 + p * 16 + b_row) * LDB + b_kh + kb;
                uint32_t t[4];
                ldm4(t, st + B_HI + r);
                bh[2*p][0] = t[0]; bh[2*p][1] = t[1];
                bh[2*p+1][0] = t[2]; bh[2*p+1][1] = t[3];
                ldm4(t, st + B_LO + r);
                bl[2*p][0] = t[0]; bl[2*p][1] = t[1];
                bl[2*p+1][0] = t[2]; bl[2*p+1][1] = t[3];
            }
            #pragma unroll
            for (int mt = 0; mt < 4; mt++)
                #pragma unroll
                for (int nt = 0; nt < 4; nt++) {
                    mma16816(acc[mt][nt], ah[mt], bh[nt]);
                    mma16816(acc[mt][nt], ah[mt], bl[nt]);
                    mma16816(acc[mt][nt], al[mt], bh[nt]);
                }
        }
        __syncthreads();
        const int nxt = it + STAGES;
        if (nxt < NITER)
            load_stage(st, Ah, Al, Bh, Bl, tid, nxt * 32);
        else
            CP_COMMIT();   // empty group keeps wait_group arithmetic uniform
    }

    // Epilogue: bias + relu, float2 stores
    #pragma unroll
    for (int nt = 0; nt < 4; nt++) {
        const int col = bn * 128 + wn * 32 + nt * 8 + (lane & 3) * 2;
        const float b0 = bias[col], b1 = bias[col + 1];
        #pragma unroll
        for (int mt = 0; mt < 4; mt++) {
            const int row = bm * 128 + wm * 64 + mt * 16 + (lane >> 2);
            float2 v0, v1;
            v0.x = fmaxf(acc[mt][nt][0] + b0, 0.0f);
            v0.y = fmaxf(acc[mt][nt][1] + b1, 0.0f);
            v1.x = fmaxf(acc[mt][nt][2] + b0, 0.0f);
            v1.y = fmaxf(acc[mt][nt][3] + b1, 0.0f);
            *reinterpret_cast<float2*>(C + (size_t)row * D_SAE + col) = v0;
            *reinterpret_cast<float2*>(C + (size_t)(row + 8) * D_SAE + col) = v1;
        }
    }
}

// ---------------------------------------------------------------------------
// Top-64 with boundary refinement:
// radix-select threshold t on approximate pre; entries > t+d are certain;
// entries in [t-d, t+d] get exact fp32 recompute + JAX tie-break (idx asc).
// ---------------------------------------------------------------------------
__global__ __launch_bounds__(256) void topk_refine_kernel(
    float* __restrict__ z, const float* __restrict__ x,
    const float* __restrict__ W, const float* __restrict__ be)
{
    const int b = blockIdx.x, tid = threadIdx.x;
    float* row = z + (size_t)b * D_SAE;

    __shared__ float xrow[K_DIM];
    __shared__ unsigned int hist[256];
    __shared__ unsigned int sh_prefix;
    __shared__ int sh_kRemain;
    __shared__ int sSlot, sNC;
    __shared__ int   cidx[128];
    __shared__ float cval[128];
    __shared__ float red[256];

    for (int i = tid; i < K_DIM; i += 256)
        xrow[i] = x[(size_t)b * K_DIM + i];

    if (tid == 0) { sh_prefix = 0u; sh_kRemain = K_TOP; sSlot = 0; sNC = 0; }
    __syncthreads();

    for (int shift = 24; shift >= 0; shift -= 8) {
        hist[tid] = 0u;
        __syncthreads();
        const unsigned int prefix = sh_prefix;
        const unsigned int hmask = (shift == 24) ? 0u : (0xFFFFFFFFu << (shift + 8));
        for (int i = tid; i < D_SAE; i += 256) {
            unsigned int bits = __float_as_uint(row[i]);
            if ((bits & hmask) == prefix)
                atomicAdd(&hist[(bits >> shift) & 0xFF], 1u);
        }
        __syncthreads();
        if (tid == 0) {
            int cum = 0;
            const int kr = sh_kRemain;
            for (int bin = 255; bin >= 0; bin--) {
                cum += (int)hist[bin];
                if (cum >= kr) {
                    sh_kRemain = kr - (cum - (int)hist[bin]);
                    sh_prefix = prefix | ((unsigned int)bin << shift);
                    break;
                }
            }
        }
        __syncthreads();
    }

    const float t = __uint_as_float(sh_prefix);
    const float dlt = 1e-3f * fmaxf(t, 1.0f);   // >> bf16-split error (~1e-5)

    for (int i = tid; i < D_SAE; i += 256) {
        const float v = row[i];
        if (v > t + dlt) {
            int s = atomicAdd(&sSlot, 1);
            g_idx[b * K_TOP + s] = i;
            g_val[b * K_TOP + s] = v;
        } else if (v >= t - dlt) {
            int c = atomicAdd(&sNC, 1);
            if (c < 128) cidx[c] = i;
            row[i] = 0.0f;      // rewritten below if kept
        } else {
            row[i] = 0.0f;
        }
    }
    __syncthreads();

    const int A = sSlot;
    const int nc = (sNC < 128) ? sNC : 128;
    const int need = K_TOP - A;

    for (int c = 0; c < nc; c++) {
        const int m = cidx[c];
        float p = 0.0f;
        for (int k = tid; k < K_DIM; k += 256)
            p = fmaf(xrow[k], W[(size_t)k * D_SAE + m], p);
        red[tid] = p;
        __syncthreads();
        for (int s = 128; s > 0; s >>= 1) {
            if (tid < s) red[tid] += red[tid + s];
            __syncthreads();
        }
        if (tid == 0) cval[c] = fmaxf(red[0] + be[m], 0.0f);
        __syncthreads();
    }

    if (tid < nc) {
        const int m = cidx[tid];
        const float v = cval[tid];
        int rank = 0;
        for (int j = 0; j < nc; j++) {
            if (j == tid) continue;
            const float vj = cval[j];
            if (vj > v || (vj == v && cidx[j] < m)) rank++;
        }
        if (rank < need) {
            row[m] = v;
            int s = atomicAdd(&sSlot, 1);
            g_idx[b * K_TOP + s] = m;
            g_val[b * K_TOP + s] = v;
        }
    }
}

// ---------------------------------------------------------------------------
// Sparse decode: x_hat[b,t,d] = b_dec[t,d] + sum_s val * W_dec[t,m,d]
// ---------------------------------------------------------------------------
__global__ __launch_bounds__(256) void decode_kernel(
    const float* __restrict__ W_dec, const float* __restrict__ b_dec,
    float* __restrict__ xhat)
{
    const int b = blockIdx.x;
    const int tid = threadIdx.x;

    __shared__ float sv[K_TOP];
    __shared__ int   si[K_TOP];
    if (tid < K_TOP) {
        sv[tid] = g_val[b * K_TOP + tid];
        si[tid] = g_idx[b * K_TOP + tid];
    }

    float  acc[12];
    size_t off[12];
    #pragma unroll
    for (int s = 0; s < 12; s++) {
        const int o = tid + s * 256;
        const int t = o / D_IN;
        const int d = o - t * D_IN;
        off[s] = (size_t)t * D_SAE * D_IN + d;
        acc[s] = b_dec[o];
    }
    __syncthreads();

    for (int i = 0; i < K_TOP; i++) {
        const float v = sv[i];
        const size_t mo = (size_t)si[i] * D_IN;
        #pragma unroll
        for (int s = 0; s < 12; s++)
            acc[s] = fmaf(v, __ldg(W_dec + off[s] + mo), acc[s]);
    }

    float* out = xhat + (size_t)b * TD;
    #pragma unroll
    for (int s = 0; s < 12; s++)
        out[tid + s * 256] = acc[s];
}

// ---------------------------------------------------------------------------
// Launch
// ---------------------------------------------------------------------------
extern "C" void kernel_launch(void* const* d_in, const int* in_sizes, int n_in,
                              void* d_out, int out_size)
{
    const float* x     = (const float*)d_in[0];
    const float* W_enc = (const float*)d_in[1];
    const float* b_enc = (const float*)d_in[2];
    const float* W_dec = (const float*)d_in[3];
    const float* b_dec = (const float*)d_in[4];

    float* xhat = (float*)d_out;
    float* z    = xhat + (size_t)B_SZ * TD;

    static int attr_set = 0;
    if (!attr_set) {
        cudaFuncSetAttribute(encode_mma_kernel,
                             cudaFuncAttributeMaxDynamicSharedMemorySize, SMEM_DYN);
        attr_set = 1;
    }

    split_x_kernel<<<(B_SZ * K_DIM) / 256, 256>>>(x);
    split_w_kernel<<<dim3(D_SAE / 32, K_DIM / 32), 256>>>(W_enc);
    encode_mma_kernel<<<dim3(D_SAE / 128, B_SZ / 128), 256, SMEM_DYN>>>(b_enc, z);
    topk_refine_kernel<<<B_SZ, 256>>>(z, x, W_enc, b_enc);
    decode_kernel<<<B_SZ, 256>>>(W_dec, b_dec, xhat);
}